// round 15
// baseline (speedup 1.0000x reference)
#include <cuda_runtime.h>
#include <stdint.h>

#define BB 4
#define SS 2048
#define DD 1024
#define EE 64
#define CC 64
#define ROWS (BB*SS)          // 8192
#define NOISE_SCALE (1.0f/64.0f)
#define HALF ((size_t)BB*SS*EE*CC)      // elements per output array

// Dynamic smem layout for gemm (floats):
#define AS_STRIDE 68
#define AS_FLOATS (2*64*AS_STRIDE)      // 8704
#define WS_FLOATS (2*64*64)             // 8192
#define SMEM_FLOATS (AS_FLOATS + WS_FLOATS)
#define SMEM_BYTES (SMEM_FLOATS*4)      // 67584

// Scratch: gates transposed [b][e][s]  (2 MB)
__device__ float g_gatesT[(size_t)BB*EE*SS];

__device__ __forceinline__ void cp_async16(uint32_t dst_smem, const void* src) {
    asm volatile("cp.async.cg.shared.global [%0], [%1], 16;" :: "r"(dst_smem), "l"(src));
}

__device__ __forceinline__ float2 ffma2(float2 a, float2 b, float2 c) {
    unsigned long long au = *reinterpret_cast<unsigned long long*>(&a);
    unsigned long long bu = *reinterpret_cast<unsigned long long*>(&b);
    unsigned long long cu = *reinterpret_cast<unsigned long long*>(&c);
    unsigned long long du;
    asm("fma.rn.f32x2 %0, %1, %2, %3;" : "=l"(du) : "l"(au), "l"(bu), "l"(cu));
    return *reinterpret_cast<float2*>(&du);
}

// ---------------------------------------------------------------------------
// Kernel 1: GEMM + noise + softmax -> gatesT.
// 128 blocks x 512 threads (16 warps/SM for latency hiding), 64x64 tile,
// thread tile 1 row x 8 experts, FFMA2 inner loop, cp.async double-buffered.
// Each output keeps a single accumulator lane scanned k-ascending -> gates
// bit-identical to the reference ranking (rel_err 1.346339e-07).
// ---------------------------------------------------------------------------
__global__ __launch_bounds__(512)
void gemm_softmax_kernel(const float* __restrict__ X,
                         const float* __restrict__ W,
                         const float* __restrict__ noise)
{
    extern __shared__ float smem[];
    float* sA = smem;               // [2][64][AS_STRIDE]
    float* sW = smem + AS_FLOATS;   // [2][64][64]

    const int tid  = threadIdx.x;
    const int tx   = tid & 7;       // expert octet: experts tx*8 .. tx*8+7
    const int ty   = tid >> 3;      // row 0..63
    const int row0 = blockIdx.x * 64;

    uint32_t smem_u32 = (uint32_t)__cvta_generic_to_shared(smem);
    const uint32_t a_base = smem_u32;
    const uint32_t w_base = smem_u32 + AS_FLOATS * 4;

    // Tile-load coordinates: 512 threads, 1024 float4 per tile -> 2 each.
    const int lr = tid >> 4;        // 0..31
    const int lc = (tid & 15) * 4;  // 0..60

    {
        const int k0 = 0;
#pragma unroll
        for (int p = 0; p < 2; p++) {
            int r = lr + p * 32;
            cp_async16(a_base + (uint32_t)((r * AS_STRIDE + lc) * 4),
                       &X[(size_t)(row0 + r) * DD + k0 + lc]);
        }
#pragma unroll
        for (int p = 0; p < 2; p++) {
            int kk = lr + p * 32;
            cp_async16(w_base + (uint32_t)((kk * 64 + lc) * 4),
                       &W[(size_t)(k0 + kk) * EE + lc]);
        }
        asm volatile("cp.async.commit_group;");
    }

    // 8 experts as 4 float2 accumulators (single lane per output, k-ascending)
    float2 acc[4];
#pragma unroll
    for (int j = 0; j < 4; j++) acc[j] = make_float2(0.f, 0.f);

    for (int it = 0; it < 16; it++) {
        const int buf = it & 1;

        asm volatile("cp.async.wait_group 0;");
        __syncthreads();

        if (it < 15) {
            const int k1 = (it + 1) * 64;
            const int nb = buf ^ 1;
            const uint32_t a_off = a_base + (uint32_t)(nb * 64 * AS_STRIDE * 4);
            const uint32_t w_off = w_base + (uint32_t)(nb * 64 * 64 * 4);
#pragma unroll
            for (int p = 0; p < 2; p++) {
                int r = lr + p * 32;
                cp_async16(a_off + (uint32_t)((r * AS_STRIDE + lc) * 4),
                           &X[(size_t)(row0 + r) * DD + k1 + lc]);
            }
#pragma unroll
            for (int p = 0; p < 2; p++) {
                int kk = lr + p * 32;
                cp_async16(w_off + (uint32_t)((kk * 64 + lc) * 4),
                           &W[(size_t)(k1 + kk) * EE + lc]);
            }
            asm volatile("cp.async.commit_group;");
        }

        const float* A  = sA + buf * 64 * AS_STRIDE + ty * AS_STRIDE;
        const float* Bm = sW + buf * 64 * 64;
#pragma unroll
        for (int kk = 0; kk < 64; kk += 2) {
            float4 b00 = *(const float4*)&Bm[(kk + 0) * 64 + tx * 8];
            float4 b01 = *(const float4*)&Bm[(kk + 0) * 64 + tx * 8 + 4];
            float4 b10 = *(const float4*)&Bm[(kk + 1) * 64 + tx * 8];
            float4 b11 = *(const float4*)&Bm[(kk + 1) * 64 + tx * 8 + 4];
            float2 av  = *(const float2*)&A[kk];
            float2 axx = make_float2(av.x, av.x);
            float2 ayy = make_float2(av.y, av.y);
            // k = kk for all 4 accs (RAW distance 4), then k = kk+1
            acc[0] = ffma2(axx, make_float2(b00.x, b00.y), acc[0]);
            acc[1] = ffma2(axx, make_float2(b00.z, b00.w), acc[1]);
            acc[2] = ffma2(axx, make_float2(b01.x, b01.y), acc[2]);
            acc[3] = ffma2(axx, make_float2(b01.z, b01.w), acc[3]);
            acc[0] = ffma2(ayy, make_float2(b10.x, b10.y), acc[0]);
            acc[1] = ffma2(ayy, make_float2(b10.z, b10.w), acc[1]);
            acc[2] = ffma2(ayy, make_float2(b11.x, b11.y), acc[2]);
            acc[3] = ffma2(ayy, make_float2(b11.z, b11.w), acc[3]);
        }
        __syncthreads();
    }

    // Epilogue: logits + noise into sW buffer 0 (reused as [row][expert])
    float* L = sW;
    {
        int row = row0 + ty;
        int e0  = tx * 8;
        const float* nz = &noise[(size_t)row * EE + e0];
        L[ty * 64 + e0 + 0] = acc[0].x + nz[0] * NOISE_SCALE;
        L[ty * 64 + e0 + 1] = acc[0].y + nz[1] * NOISE_SCALE;
        L[ty * 64 + e0 + 2] = acc[1].x + nz[2] * NOISE_SCALE;
        L[ty * 64 + e0 + 3] = acc[1].y + nz[3] * NOISE_SCALE;
        L[ty * 64 + e0 + 4] = acc[2].x + nz[4] * NOISE_SCALE;
        L[ty * 64 + e0 + 5] = acc[2].y + nz[5] * NOISE_SCALE;
        L[ty * 64 + e0 + 6] = acc[3].x + nz[6] * NOISE_SCALE;
        L[ty * 64 + e0 + 7] = acc[3].y + nz[7] * NOISE_SCALE;
    }
    __syncthreads();

    // Softmax per row (threads 0..63), write transposed gates.
    if (tid < 64) {
        int r   = tid;
        int row = row0 + r;
        int b   = row / SS;
        int s   = row % SS;
        float m = -1e30f;
#pragma unroll
        for (int e = 0; e < EE; e++) m = fmaxf(m, L[r * 64 + e]);
        float sum = 0.0f;
#pragma unroll
        for (int e = 0; e < EE; e++) {
            float t = expf(L[r * 64 + e] - m);
            L[r * 64 + e] = t;
            sum += t;
        }
        float inv = 1.0f / sum;
#pragma unroll
        for (int e = 0; e < EE; e++) {
            g_gatesT[((size_t)b * EE + e) * SS + s] = L[r * 64 + e] * inv;
        }
    }
}

// ---------------------------------------------------------------------------
// Kernel 2: register-resident top-64 (unchanged from R13/R14 wins).
// ---------------------------------------------------------------------------
__global__ __launch_bounds__(512)
void topk_kernel(float* __restrict__ mask_out,
                 float* __restrict__ comb_out)
{
    __shared__ unsigned long long cand[512];
    __shared__ int hist[256];
    __shared__ int warpsum[8], woff[8];
    __shared__ unsigned long long s_prefix, s_thresh;
    __shared__ int s_need, s_done, s_cnt;

    const int tid  = threadIdx.x;
    const int lane = tid & 31;
    const int wrp  = tid >> 5;
    const int b = blockIdx.x >> 6;
    const int e = blockIdx.x & 63;

    unsigned long long k[4];
    const float* col = &g_gatesT[((size_t)b * EE + e) * SS];
#pragma unroll
    for (int j = 0; j < 4; j++) {
        int i = tid + j * 512;
        unsigned int fb = __float_as_uint(col[i]);   // softmax gates > 0
        k[j] = ((unsigned long long)fb << 32) | (unsigned int)(~i);
    }
    if (tid == 0) { s_done = 0; s_need = CC; s_prefix = 0ULL; }
    __syncthreads();

    for (int shift = 56; shift >= 0; shift -= 8) {
        if (s_done) break;
        const unsigned long long pf = s_prefix;
        const int need = s_need;
        if (tid < 256) hist[tid] = 0;
        __syncthreads();
#pragma unroll
        for (int j = 0; j < 4; j++) {
            bool active = (shift == 56) || ((k[j] >> (shift + 8)) == pf);
            if (active) atomicAdd(&hist[(int)((k[j] >> shift) & 255)], 1);
        }
        __syncthreads();

        int own = 0, sfx = 0;
        if (tid < 256) {
            own = hist[tid];
            int v = own;
#pragma unroll
            for (int off = 1; off < 32; off <<= 1) {
                int t = __shfl_down_sync(0xFFFFFFFFu, v, off);
                if (lane + off < 32) v += t;
            }
            if (lane == 0) warpsum[wrp] = v;
            sfx = v;
        }
        __syncthreads();
        if (tid < 8) {
            int acc = 0;
            for (int w = 7; w > tid; w--) acc += warpsum[w];
            woff[tid] = acc;
        }
        __syncthreads();

        if (tid < 256) {
            int c     = sfx + woff[wrp];
            int above = c - own;
            if (c >= need && above < need) {
                int got = (CC - need) + c;
                unsigned long long np = (pf << 8) | (unsigned long long)tid;
                if (got <= 512 || shift == 0) {
                    s_thresh = np << shift;
                    s_done = 1;
                } else {
                    s_need = need - above;
                    s_prefix = np;
                }
            }
        }
        __syncthreads();
    }

    cand[tid] = 0ULL;
    if (tid == 0) s_cnt = 0;
    __syncthreads();
    {
        const unsigned long long T = s_thresh;
#pragma unroll
        for (int j = 0; j < 4; j++) {
            if (k[j] >= T) {
                int p = atomicAdd(&s_cnt, 1);
                if (p < 512) cand[p] = k[j];
            }
        }
    }
    __syncthreads();

    int cnt = s_cnt;
    int nsort = 64;
    while (nsort < cnt && nsort < 512) nsort <<= 1;

    for (int k2 = 2; k2 <= nsort; k2 <<= 1) {
        for (int j = k2 >> 1; j > 0; j >>= 1) {
            if (tid < (nsort >> 1)) {
                int i   = ((tid & ~(j - 1)) << 1) | (tid & (j - 1));
                int ixj = i | j;
                bool desc = ((i & k2) == 0);
                unsigned long long a = cand[i];
                unsigned long long c = cand[ixj];
                if ((a < c) == desc) { cand[i] = c; cand[ixj] = a; }
            }
            __syncthreads();
        }
    }

    if (tid < CC) {
        unsigned long long kk = cand[tid];
        int   s = (int)(~(unsigned int)kk);
        float v = __uint_as_float((unsigned int)(kk >> 32));
        size_t idx = ((((size_t)b * SS + s) * EE + e) << 6) + tid;
        mask_out[idx] = 1.0f;
        comb_out[idx] = v;
    }
}

// ---------------------------------------------------------------------------
// STRICTLY SERIAL pipeline: memset -> gemm -> topk, single stream.
// ---------------------------------------------------------------------------
extern "C" void kernel_launch(void* const* d_in, const int* in_sizes, int n_in,
                              void* d_out, int out_size)
{
    const float* X     = (const float*)d_in[0];   // [B,S,D]
    const float* W     = (const float*)d_in[1];   // [D,E]
    const float* noise = (const float*)d_in[2];   // [B,S,E]
    float* out = (float*)d_out;

    cudaFuncSetAttribute(gemm_softmax_kernel,
                         cudaFuncAttributeMaxDynamicSharedMemorySize, SMEM_BYTES);

    cudaMemsetAsync(out, 0, (size_t)out_size * sizeof(float), 0);
    gemm_softmax_kernel<<<ROWS / 64, 512, SMEM_BYTES>>>(X, W, noise);
    topk_kernel<<<BB * EE, 512>>>(out, out + HALF);
}

// round 16
// speedup vs baseline: 2.2474x; 2.2474x over previous
#include <cuda_runtime.h>
#include <stdint.h>

#define BB 4
#define SS 2048
#define DD 1024
#define EE 64
#define CC 64
#define ROWS (BB*SS)          // 8192
#define NOISE_SCALE (1.0f/64.0f)
#define HALF ((size_t)BB*SS*EE*CC)      // elements per output array

// Dynamic smem: 3-stage pipeline
//   A: 3 buffers x 64 rows x 68 stride
//   W: 3 buffers x 64 k x 64 experts
#define AS_STRIDE 68
#define A_BUF_FLOATS (64*AS_STRIDE)     // 4352
#define W_BUF_FLOATS (64*64)            // 4096
#define AS_FLOATS (3*A_BUF_FLOATS)      // 13056
#define WS_FLOATS (3*W_BUF_FLOATS)      // 12288
#define SMEM_BYTES ((AS_FLOATS + WS_FLOATS)*4)   // 101376

// Scratch: gates transposed [b][e][s]  (2 MB)
__device__ float g_gatesT[(size_t)BB*EE*SS];

__device__ __forceinline__ void cp_async16(uint32_t dst_smem, const void* src) {
    asm volatile("cp.async.cg.shared.global [%0], [%1], 16;" :: "r"(dst_smem), "l"(src));
}

__device__ __forceinline__ float2 ffma2(float2 a, float2 b, float2 c) {
    unsigned long long au = *reinterpret_cast<unsigned long long*>(&a);
    unsigned long long bu = *reinterpret_cast<unsigned long long*>(&b);
    unsigned long long cu = *reinterpret_cast<unsigned long long*>(&c);
    unsigned long long du;
    asm("fma.rn.f32x2 %0, %1, %2, %3;" : "=l"(du) : "l"(au), "l"(bu), "l"(cu));
    return *reinterpret_cast<float2*>(&du);
}

// ---------------------------------------------------------------------------
// Kernel 1: GEMM + noise + softmax -> gatesT.
// R14's proven 256-thread / 64x64-tile / 4x4(FFMA2) compute, upgraded to a
// 3-stage cp.async pipeline (prefetch 2 iters ahead, wait_group 1, ONE
// barrier per iteration) and RAW-respaced FFMA2 (acc reuse distance 8).
// Per-output accumulation order unchanged (k-ascending, single lane)
// -> gates bit-identical to reference ranking (rel_err 1.346339e-07).
// ---------------------------------------------------------------------------
__global__ __launch_bounds__(256)
void gemm_softmax_kernel(const float* __restrict__ X,
                         const float* __restrict__ W,
                         const float* __restrict__ noise)
{
    extern __shared__ float smem[];
    float* sA = smem;               // [3][64][AS_STRIDE]
    float* sW = smem + AS_FLOATS;   // [3][64][64]

    const int tid  = threadIdx.x;
    const int tx   = tid & 15;
    const int ty   = tid >> 4;
    const int row0 = blockIdx.x * 64;

    uint32_t smem_u32 = (uint32_t)__cvta_generic_to_shared(smem);
    const uint32_t a_base = smem_u32;
    const uint32_t w_base = smem_u32 + AS_FLOATS * 4;

    const int lr = tid >> 4;
    const int lc = (tid & 15) * 4;

    // Preload tiles 0 and 1 into buffers 0 and 1 (two commit groups).
#pragma unroll
    for (int pre = 0; pre < 2; pre++) {
        const int k0 = pre * 64;
        const uint32_t a_off = a_base + (uint32_t)(pre * A_BUF_FLOATS * 4);
        const uint32_t w_off = w_base + (uint32_t)(pre * W_BUF_FLOATS * 4);
#pragma unroll
        for (int p = 0; p < 4; p++) {
            int r = lr + p * 16;
            cp_async16(a_off + (uint32_t)((r * AS_STRIDE + lc) * 4),
                       &X[(size_t)(row0 + r) * DD + k0 + lc]);
        }
#pragma unroll
        for (int p = 0; p < 4; p++) {
            int kk = lr + p * 16;
            cp_async16(w_off + (uint32_t)((kk * 64 + lc) * 4),
                       &W[(size_t)(k0 + kk) * EE + lc]);
        }
        asm volatile("cp.async.commit_group;");
    }

    float2 acc[4][2];
#pragma unroll
    for (int i = 0; i < 4; i++) {
        acc[i][0] = make_float2(0.f, 0.f);
        acc[i][1] = make_float2(0.f, 0.f);
    }

    for (int it = 0; it < 16; it++) {
        const int buf = it % 3;

        // Tile `it` is complete once <=1 newer group remains outstanding.
        asm volatile("cp.async.wait_group 1;");
        // Also guarantees every warp finished computing on buffer (it-1)%3,
        // which prefetch below (targeting (it+2)%3 == (it-1)%3) will refill.
        __syncthreads();

        if (it < 14) {
            const int k1 = (it + 2) * 64;
            const int nb = (it + 2) % 3;
            const uint32_t a_off = a_base + (uint32_t)(nb * A_BUF_FLOATS * 4);
            const uint32_t w_off = w_base + (uint32_t)(nb * W_BUF_FLOATS * 4);
#pragma unroll
            for (int p = 0; p < 4; p++) {
                int r = lr + p * 16;
                cp_async16(a_off + (uint32_t)((r * AS_STRIDE + lc) * 4),
                           &X[(size_t)(row0 + r) * DD + k1 + lc]);
            }
#pragma unroll
            for (int p = 0; p < 4; p++) {
                int kk = lr + p * 16;
                cp_async16(w_off + (uint32_t)((kk * 64 + lc) * 4),
                           &W[(size_t)(k1 + kk) * EE + lc]);
            }
            asm volatile("cp.async.commit_group;");
        } else {
            // Keep group-count semantics uniform for wait_group 1.
            asm volatile("cp.async.commit_group;");
        }

        const float* A  = sA + buf * A_BUF_FLOATS;
        const float* Bm = sW + buf * W_BUF_FLOATS;
#pragma unroll
        for (int kk = 0; kk < 64; kk += 2) {
            float4 bq0 = *(const float4*)&Bm[(kk + 0) * 64 + tx * 4];
            float4 bq1 = *(const float4*)&Bm[(kk + 1) * 64 + tx * 4];
            float2 b0p01 = make_float2(bq0.x, bq0.y);
            float2 b0p23 = make_float2(bq0.z, bq0.w);
            float2 b1p01 = make_float2(bq1.x, bq1.y);
            float2 b1p23 = make_float2(bq1.z, bq1.w);
            float2 av[4];
#pragma unroll
            for (int i = 0; i < 4; i++)
                av[i] = *(const float2*)&A[(ty * 4 + i) * AS_STRIDE + kk];
            // k = kk for all rows (RAW distance 8), then k = kk+1:
            // per-accumulator order is still kk before kk+1 -> bit-identical.
#pragma unroll
            for (int i = 0; i < 4; i++) {
                float2 axx = make_float2(av[i].x, av[i].x);
                acc[i][0] = ffma2(axx, b0p01, acc[i][0]);
                acc[i][1] = ffma2(axx, b0p23, acc[i][1]);
            }
#pragma unroll
            for (int i = 0; i < 4; i++) {
                float2 ayy = make_float2(av[i].y, av[i].y);
                acc[i][0] = ffma2(ayy, b1p01, acc[i][0]);
                acc[i][1] = ffma2(ayy, b1p23, acc[i][1]);
            }
        }
    }
    __syncthreads();

    // Epilogue: logits + noise into sW buffer 0 (reused as [row][expert])
    float* L = sW;
#pragma unroll
    for (int i = 0; i < 4; i++) {
        int r   = ty * 4 + i;
        int row = row0 + r;
        int e0  = tx * 4;
        L[r * 64 + e0 + 0] = acc[i][0].x + noise[(size_t)row * EE + e0 + 0] * NOISE_SCALE;
        L[r * 64 + e0 + 1] = acc[i][0].y + noise[(size_t)row * EE + e0 + 1] * NOISE_SCALE;
        L[r * 64 + e0 + 2] = acc[i][1].x + noise[(size_t)row * EE + e0 + 2] * NOISE_SCALE;
        L[r * 64 + e0 + 3] = acc[i][1].y + noise[(size_t)row * EE + e0 + 3] * NOISE_SCALE;
    }
    __syncthreads();

    if (tid < 64) {
        int r   = tid;
        int row = row0 + r;
        int b   = row / SS;
        int s   = row % SS;
        float m = -1e30f;
#pragma unroll
        for (int e = 0; e < EE; e++) m = fmaxf(m, L[r * 64 + e]);
        float sum = 0.0f;
#pragma unroll
        for (int e = 0; e < EE; e++) {
            float t = expf(L[r * 64 + e] - m);
            L[r * 64 + e] = t;
            sum += t;
        }
        float inv = 1.0f / sum;
#pragma unroll
        for (int e = 0; e < EE; e++) {
            g_gatesT[((size_t)b * EE + e) * SS + s] = L[r * 64 + e] * inv;
        }
    }
}

// ---------------------------------------------------------------------------
// Kernel 2: register-resident top-64 (unchanged from R13/R14 wins).
// ---------------------------------------------------------------------------
__global__ __launch_bounds__(512)
void topk_kernel(float* __restrict__ mask_out,
                 float* __restrict__ comb_out)
{
    __shared__ unsigned long long cand[512];
    __shared__ int hist[256];
    __shared__ int warpsum[8], woff[8];
    __shared__ unsigned long long s_prefix, s_thresh;
    __shared__ int s_need, s_done, s_cnt;

    const int tid  = threadIdx.x;
    const int lane = tid & 31;
    const int wrp  = tid >> 5;
    const int b = blockIdx.x >> 6;
    const int e = blockIdx.x & 63;

    unsigned long long k[4];
    const float* col = &g_gatesT[((size_t)b * EE + e) * SS];
#pragma unroll
    for (int j = 0; j < 4; j++) {
        int i = tid + j * 512;
        unsigned int fb = __float_as_uint(col[i]);   // softmax gates > 0
        k[j] = ((unsigned long long)fb << 32) | (unsigned int)(~i);
    }
    if (tid == 0) { s_done = 0; s_need = CC; s_prefix = 0ULL; }
    __syncthreads();

    for (int shift = 56; shift >= 0; shift -= 8) {
        if (s_done) break;
        const unsigned long long pf = s_prefix;
        const int need = s_need;
        if (tid < 256) hist[tid] = 0;
        __syncthreads();
#pragma unroll
        for (int j = 0; j < 4; j++) {
            bool active = (shift == 56) || ((k[j] >> (shift + 8)) == pf);
            if (active) atomicAdd(&hist[(int)((k[j] >> shift) & 255)], 1);
        }
        __syncthreads();

        int own = 0, sfx = 0;
        if (tid < 256) {
            own = hist[tid];
            int v = own;
#pragma unroll
            for (int off = 1; off < 32; off <<= 1) {
                int t = __shfl_down_sync(0xFFFFFFFFu, v, off);
                if (lane + off < 32) v += t;
            }
            if (lane == 0) warpsum[wrp] = v;
            sfx = v;
        }
        __syncthreads();
        if (tid < 8) {
            int acc = 0;
            for (int w = 7; w > tid; w--) acc += warpsum[w];
            woff[tid] = acc;
        }
        __syncthreads();

        if (tid < 256) {
            int c     = sfx + woff[wrp];
            int above = c - own;
            if (c >= need && above < need) {
                int got = (CC - need) + c;
                unsigned long long np = (pf << 8) | (unsigned long long)tid;
                if (got <= 512 || shift == 0) {
                    s_thresh = np << shift;
                    s_done = 1;
                } else {
                    s_need = need - above;
                    s_prefix = np;
                }
            }
        }
        __syncthreads();
    }

    cand[tid] = 0ULL;
    if (tid == 0) s_cnt = 0;
    __syncthreads();
    {
        const unsigned long long T = s_thresh;
#pragma unroll
        for (int j = 0; j < 4; j++) {
            if (k[j] >= T) {
                int p = atomicAdd(&s_cnt, 1);
                if (p < 512) cand[p] = k[j];
            }
        }
    }
    __syncthreads();

    int cnt = s_cnt;
    int nsort = 64;
    while (nsort < cnt && nsort < 512) nsort <<= 1;

    for (int k2 = 2; k2 <= nsort; k2 <<= 1) {
        for (int j = k2 >> 1; j > 0; j >>= 1) {
            if (tid < (nsort >> 1)) {
                int i   = ((tid & ~(j - 1)) << 1) | (tid & (j - 1));
                int ixj = i | j;
                bool desc = ((i & k2) == 0);
                unsigned long long a = cand[i];
                unsigned long long c = cand[ixj];
                if ((a < c) == desc) { cand[i] = c; cand[ixj] = a; }
            }
            __syncthreads();
        }
    }

    if (tid < CC) {
        unsigned long long kk = cand[tid];
        int   s = (int)(~(unsigned int)kk);
        float v = __uint_as_float((unsigned int)(kk >> 32));
        size_t idx = ((((size_t)b * SS + s) * EE + e) << 6) + tid;
        mask_out[idx] = 1.0f;
        comb_out[idx] = v;
    }
}

// ---------------------------------------------------------------------------
// STRICTLY SERIAL pipeline: memset -> gemm -> topk, single stream.
// ---------------------------------------------------------------------------
extern "C" void kernel_launch(void* const* d_in, const int* in_sizes, int n_in,
                              void* d_out, int out_size)
{
    const float* X     = (const float*)d_in[0];   // [B,S,D]
    const float* W     = (const float*)d_in[1];   // [D,E]
    const float* noise = (const float*)d_in[2];   // [B,S,E]
    float* out = (float*)d_out;

    cudaFuncSetAttribute(gemm_softmax_kernel,
                         cudaFuncAttributeMaxDynamicSharedMemorySize, SMEM_BYTES);

    cudaMemsetAsync(out, 0, (size_t)out_size * sizeof(float), 0);
    gemm_softmax_kernel<<<ROWS / 64, 256, SMEM_BYTES>>>(X, W, noise);
    topk_kernel<<<BB * EE, 512>>>(out, out + HALF);
}